// round 6
// baseline (speedup 1.0000x reference)
#include <cuda_runtime.h>
#include <cuda_fp16.h>

// WeightedDiceLoss (sm_103a) — fp16 hsum ring, small CTAs, high CTA residency.
// weight = 1 + 5*|boxavg31(target) - target|, zero pad, /961
// out = 1 - (2*sum(in*t*w) + 1) / (sum(in*w) + sum(t*w) + 1)

#define Wd    512
#define Hd    512
#define Rr    64                   // output rows per CTA slab
#define HALO  15
#define SLABR (Rr + 2*HALO)        // 94 rows streamed
#define RING  48                   // fp16 hsum ring rows (48 KB)
#define NCH   4                    // consumer chunks of 16 rows
#define INV_KK2 (1.0f/961.0f)

__device__ float g_part[3 * 1024];
__device__ unsigned int g_count = 0;

__global__ __launch_bounds__(256, 4)
void wdice_main(const float* __restrict__ input,
                const float* __restrict__ target,
                float* __restrict__ out)
{
    extern __shared__ __half HS[];          // [RING][512] fp16 hsum ring
    __shared__ float red[24];
    __shared__ unsigned int sIsLast;

    const int tid  = threadIdx.x;
    const int wid  = tid >> 5;              // 0..7
    const int lane = tid & 31;
    const int img  = blockIdx.x >> 3;       // 8 slabs per image
    const int slab = blockIdx.x & 7;
    const int r0   = slab * Rr;
    const size_t imgOff = (size_t)img * (size_t)(Hd * Wd);

    // ---- Producer: 8 warps build 16 hsum rows per call (2 rows/warp).
    auto produce = [&](int pr) {
        #pragma unroll
        for (int sub = 0; sub < 2; sub++) {
            const int j = pr + sub * 8 + wid;
            if (j >= SLABR) continue;
            const int gr = r0 - HALO + j;
            uint4* dst = (uint4*)((char*)HS + (size_t)(j % RING) * 1024 + lane * 32);
            if (gr < 0 || gr >= Hd) {
                const uint4 z = make_uint4(0, 0, 0, 0);
                dst[0] = z; dst[1] = z;
                continue;
            }
            float v[16];
            const float4* row = (const float4*)(target + imgOff + (size_t)gr * Wd);
            #pragma unroll
            for (int q = 0; q < 4; q++) {
                float4 f = row[lane * 4 + q];
                v[4*q+0] = f.x; v[4*q+1] = f.y; v[4*q+2] = f.z; v[4*q+3] = f.w;
            }
            #pragma unroll
            for (int i = 1; i < 16; i++) v[i] += v[i-1];
            float tot = v[15], s = tot;
            #pragma unroll
            for (int o = 1; o < 32; o <<= 1) {
                float n = __shfl_up_sync(0xffffffffu, s, o);
                if (lane >= o) s += n;
            }
            const float ex = s - tot;
            #pragma unroll
            for (int i = 0; i < 16; i++) v[i] += ex;
            const float vtop = v[15];
            float h[16];
            #pragma unroll
            for (int i = 0; i < 16; i++) {
                float prv = __shfl_up_sync(0xffffffffu, v[i], 1);
                if (lane == 0) prv = 0.f;
                float hiP;
                if (i == 0) hiP = vtop;
                else {
                    float nxt = __shfl_down_sync(0xffffffffu, v[i-1], 1);
                    hiP = (lane == 31) ? vtop : nxt;
                }
                h[i] = hiP - prv;
            }
            unsigned up[8];
            #pragma unroll
            for (int p = 0; p < 8; p++) {
                __half2 hh = __floats2half2_rn(h[2*p], h[2*p+1]);
                up[p] = *reinterpret_cast<unsigned*>(&hh);
            }
            dst[0] = make_uint4(up[0], up[1], up[2], up[3]);
            dst[1] = make_uint4(up[4], up[5], up[6], up[7]);
        }
    };

    // Prime ring with slab rows 0..47
    produce(0); produce(16); produce(32);
    __syncthreads();

    // ---- Consumer: thread = column pair ct (cols 2ct, 2ct+1).
    const int ct = tid;
    const __half2* HSh = (const __half2*)HS;     // row stride 256 half2
    float2 vs = make_float2(0.f, 0.f);
    #pragma unroll
    for (int j = 0; j <= 2 * HALO; j++) {        // rows 0..30
        float2 a = __half22float2(HSh[j * 256 + ct]);
        vs.x += a.x; vs.y += a.y;
    }

    float2 aI = make_float2(0.f, 0.f);
    float2 aA = make_float2(0.f, 0.f);
    float2 aB = make_float2(0.f, 0.f);
    const float2* tgt = (const float2*)(target + imgOff + (size_t)r0 * Wd) + ct;
    const float2* inp = (const float2*)(input  + imgOff + (size_t)r0 * Wd) + ct;

    #pragma unroll
    for (int ch = 0; ch < NCH; ch++) {
        const int base = (16 * ch) % RING;
        #pragma unroll
        for (int kk = 0; kk < 16; kk++) {
            const int k = ch * 16 + kk;
            const float2 t2 = tgt[k * 256];
            const float2 i2 = inp[k * 256];
            const float w0 = fmaf(5.f, fabsf(fmaf(vs.x, INV_KK2, -t2.x)), 1.f);
            const float w1 = fmaf(5.f, fabsf(fmaf(vs.y, INV_KK2, -t2.y)), 1.f);
            const float tw0 = t2.x * w0, tw1 = t2.y * w1;
            aI.x = fmaf(i2.x, tw0, aI.x);  aI.y = fmaf(i2.y, tw1, aI.y);
            aA.x = fmaf(i2.x, w0,  aA.x);  aA.y = fmaf(i2.y, w1,  aA.y);
            aB.x += tw0;                   aB.y += tw1;

            if (k < Rr - 1) {
                int ao = base + 31 + kk; if (ao >= RING) ao -= RING;
                const int so = base + kk;
                const float2 ar = __half22float2(HSh[ao * 256 + ct]);
                const float2 sr = __half22float2(HSh[so * 256 + ct]);
                vs.x += ar.x - sr.x;
                vs.y += ar.y - sr.y;
            }
        }
        __syncthreads();                 // rows ch*16..+15 dead
        if (ch < NCH - 1) {
            produce(48 + ch * 16);       // refill same ring slots
            __syncthreads();
        }
    }

    float rI = aI.x + aI.y, rA = aA.x + aA.y, rB = aB.x + aB.y;

    // ---- Block reduction (fixed order -> deterministic)
    #pragma unroll
    for (int o = 16; o > 0; o >>= 1) {
        rI += __shfl_down_sync(0xffffffffu, rI, o);
        rA += __shfl_down_sync(0xffffffffu, rA, o);
        rB += __shfl_down_sync(0xffffffffu, rB, o);
    }
    if (lane == 0) { red[wid] = rI; red[8 + wid] = rA; red[16 + wid] = rB; }
    __syncthreads();
    if (tid == 0) {
        float I = 0.f, A = 0.f, B = 0.f;
        #pragma unroll
        for (int i = 0; i < 8; i++) { I += red[i]; A += red[8 + i]; B += red[16 + i]; }
        g_part[blockIdx.x * 3 + 0] = I;
        g_part[blockIdx.x * 3 + 1] = A;
        g_part[blockIdx.x * 3 + 2] = B;
        __threadfence();
        sIsLast = (atomicAdd(&g_count, 1u) == gridDim.x - 1u);
    }
    __syncthreads();

    if (sIsLast) {
        const int nb = gridDim.x;
        float i = 0.f, a = 0.f, b = 0.f;
        for (int j = tid; j < nb; j += 256) {
            i += g_part[3 * j + 0];
            a += g_part[3 * j + 1];
            b += g_part[3 * j + 2];
        }
        #pragma unroll
        for (int o = 16; o > 0; o >>= 1) {
            i += __shfl_down_sync(0xffffffffu, i, o);
            a += __shfl_down_sync(0xffffffffu, a, o);
            b += __shfl_down_sync(0xffffffffu, b, o);
        }
        __syncthreads();
        if (lane == 0) { red[wid] = i; red[8 + wid] = a; red[16 + wid] = b; }
        __syncthreads();
        if (tid == 0) {
            float I = 0.f, A = 0.f, B = 0.f;
            #pragma unroll
            for (int q = 0; q < 8; q++) { I += red[q]; A += red[8 + q]; B += red[16 + q]; }
            out[0] = 1.f - (2.f * I + 1.f) / (A + B + 1.f);
            g_count = 0;
        }
    }
}

extern "C" void kernel_launch(void* const* d_in, const int* in_sizes, int n_in,
                              void* d_out, int out_size)
{
    const float* input  = (const float*)d_in[0];
    const float* target = (const float*)d_in[1];
    const int nImg = in_sizes[0] / (Hd * Wd);
    const int grid = nImg * (Hd / Rr);              // 512 for B=64
    const size_t smem = (size_t)RING * Wd * sizeof(__half);   // 49152 B

    cudaFuncSetAttribute(wdice_main,
                         cudaFuncAttributeMaxDynamicSharedMemorySize, (int)smem);
    wdice_main<<<grid, 256, smem>>>(input, target, (float*)d_out);
}

// round 8
// speedup vs baseline: 1.0660x; 1.0660x over previous
#include <cuda_runtime.h>

// WeightedDiceLoss (sm_103a) — R3 architecture + corrected XOR-swizzled hsum
// ring (conflict-free producer STS.128 and consumer LDS.32).
// weight = 1 + 5*|boxavg31(target) - target|, zero pad, /961
// out = 1 - (2*sum(in*t*w) + 1) / (sum(in*w) + sum(t*w) + 1)

#define Wd    512
#define Hd    512
#define Rr    128
#define HALO  15
#define SLABR (Rr + 2*HALO)        // 158
#define RING  48
#define NCHUNK (Rr / 16)           // 8
#define INV_KK2 (1.0f/961.0f)

// physical column for logical column c: XOR 16B-unit index u=c>>2 low 3 bits
// with bits 3-5 of u  ==>  c ^ (((c>>5)&7)<<2)
__device__ __forceinline__ int swz(int c) { return c ^ (((c >> 5) & 7) << 2); }

__device__ float g_part[3 * 1024];
__device__ unsigned int g_count = 0;

__global__ __launch_bounds__(512, 2)
void wdice_main(const float* __restrict__ input,
                const float* __restrict__ target,
                int slabsPerImg,
                float* __restrict__ out)
{
    extern __shared__ float HS[];           // [RING][512] swizzled hsum rows
    const int tid  = threadIdx.x;
    const int wid  = tid >> 5;
    const int lane = tid & 31;
    const int img  = blockIdx.x / slabsPerImg;
    const int slab = blockIdx.x % slabsPerImg;
    const int r0   = slab * Rr;
    const size_t imgOff = (size_t)img * (size_t)(Hd * Wd);

    // ---- Producer: warp `wid` computes hsum of target row (r0-15+j),
    // stores swizzled into ring slot j%RING. One row per warp, 16 rows/call.
    auto produce = [&](int pr) {
        const int j = pr + wid;
        if (j >= SLABR) return;
        const int gr = r0 - HALO + j;
        float4* dstRow = (float4*)(HS + (j % RING) * Wd);
        const int sL = (lane >> 1) & 7;      // = (u>>3)&7 for u = 4*lane+p
        if (gr < 0 || gr >= Hd) {
            const float4 z = make_float4(0.f, 0.f, 0.f, 0.f);
            #pragma unroll
            for (int p = 0; p < 4; p++) dstRow[(4 * lane + p) ^ sL] = z;
            return;
        }
        float v[16];
        const float4* row = (const float4*)(target + imgOff + (size_t)gr * Wd);
        #pragma unroll
        for (int q = 0; q < 4; q++) {
            float4 f = row[lane * 4 + q];
            v[4*q+0] = f.x; v[4*q+1] = f.y; v[4*q+2] = f.z; v[4*q+3] = f.w;
        }
        #pragma unroll
        for (int i = 1; i < 16; i++) v[i] += v[i-1];
        float tot = v[15], s = tot;
        #pragma unroll
        for (int o = 1; o < 32; o <<= 1) {
            float n = __shfl_up_sync(0xffffffffu, s, o);
            if (lane >= o) s += n;
        }
        const float ex = s - tot;
        #pragma unroll
        for (int i = 0; i < 16; i++) v[i] += ex;
        const float vtop = v[15];

        float h[16];
        #pragma unroll
        for (int i = 0; i < 16; i++) {
            float prv = __shfl_up_sync(0xffffffffu, v[i], 1);
            if (lane == 0) prv = 0.f;
            float hiP;
            if (i == 0) hiP = vtop;
            else {
                float nxt = __shfl_down_sync(0xffffffffu, v[i-1], 1);
                hiP = (lane == 31) ? vtop : nxt;
            }
            h[i] = hiP - prv;
        }
        // swizzled conflict-free float4 stores (bijective unit permutation)
        #pragma unroll
        for (int p = 0; p < 4; p++)
            dstRow[(4 * lane + p) ^ sL] =
                make_float4(h[4*p], h[4*p+1], h[4*p+2], h[4*p+3]);
    };

    produce(0); produce(16); produce(32);
    __syncthreads();

    // ---- Consumer: thread = column c (fixed swizzled offset qc).
    const int c  = tid;
    const int qc = swz(c);
    float vsum = 0.f;
    #pragma unroll
    for (int j = 0; j <= 2 * HALO; j++)
        vsum += HS[j * Wd + qc];

    float aI = 0.f, aA = 0.f, aB = 0.f;
    const float* inp = input  + imgOff + (size_t)r0 * Wd + c;
    const float* tgt = target + imgOff + (size_t)r0 * Wd + c;

    #pragma unroll
    for (int ch = 0; ch < NCHUNK; ch++) {
        #pragma unroll
        for (int kk = 0; kk < 16; kk++) {
            const int k = ch * 16 + kk;
            const int jAdd = ((k + 31) % RING) * Wd;
            const int jSub = (k % RING) * Wd;

            const float t  = tgt[k * Wd];
            const float in = inp[k * Wd];
            const float w  = fmaf(5.f, fabsf(fmaf(vsum, INV_KK2, -t)), 1.f);
            const float tw = t * w;
            aI = fmaf(in, tw, aI);
            aA = fmaf(in, w,  aA);
            aB += tw;

            if (k < Rr - 1)
                vsum += (HS[jAdd + qc] - HS[jSub + qc]);
        }
        __syncthreads();
        if (ch < NCHUNK - 1) {
            produce(48 + ch * 16);
            __syncthreads();
        }
    }

    // ---- Block reduction (fixed order -> deterministic)
    #pragma unroll
    for (int o = 16; o > 0; o >>= 1) {
        aI += __shfl_down_sync(0xffffffffu, aI, o);
        aA += __shfl_down_sync(0xffffffffu, aA, o);
        aB += __shfl_down_sync(0xffffffffu, aB, o);
    }
    if (lane == 0) { HS[wid] = aI; HS[16 + wid] = aA; HS[32 + wid] = aB; }
    __syncthreads();
    __shared__ unsigned int sIsLast;
    if (tid == 0) {
        float I = 0.f, A = 0.f, B = 0.f;
        #pragma unroll
        for (int i = 0; i < 16; i++) { I += HS[i]; A += HS[16 + i]; B += HS[32 + i]; }
        g_part[blockIdx.x * 3 + 0] = I;
        g_part[blockIdx.x * 3 + 1] = A;
        g_part[blockIdx.x * 3 + 2] = B;
        __threadfence();
        sIsLast = (atomicAdd(&g_count, 1u) == gridDim.x - 1u);
    }
    __syncthreads();

    if (sIsLast) {
        const int nb = gridDim.x;
        float i = 0.f, a = 0.f, b = 0.f;
        for (int j = tid; j < nb; j += 512) {
            i += g_part[3 * j + 0];
            a += g_part[3 * j + 1];
            b += g_part[3 * j + 2];
        }
        #pragma unroll
        for (int o = 16; o > 0; o >>= 1) {
            i += __shfl_down_sync(0xffffffffu, i, o);
            a += __shfl_down_sync(0xffffffffu, a, o);
            b += __shfl_down_sync(0xffffffffu, b, o);
        }
        __syncthreads();
        if (lane == 0) { HS[wid] = i; HS[16 + wid] = a; HS[32 + wid] = b; }
        __syncthreads();
        if (tid == 0) {
            float I = 0.f, A = 0.f, B = 0.f;
            #pragma unroll
            for (int q = 0; q < 16; q++) { I += HS[q]; A += HS[16 + q]; B += HS[32 + q]; }
            out[0] = 1.f - (2.f * I + 1.f) / (A + B + 1.f);
            g_count = 0;
        }
    }
}

extern "C" void kernel_launch(void* const* d_in, const int* in_sizes, int n_in,
                              void* d_out, int out_size)
{
    const float* input  = (const float*)d_in[0];
    const float* target = (const float*)d_in[1];
    const int nImg = in_sizes[0] / (Hd * Wd);
    const int slabsPerImg = Hd / Rr;               // 4
    const int grid = nImg * slabsPerImg;           // 256
    const size_t smem = (size_t)RING * Wd * sizeof(float);   // 98304 B

    cudaFuncSetAttribute(wdice_main,
                         cudaFuncAttributeMaxDynamicSharedMemorySize, (int)smem);
    wdice_main<<<grid, 512, smem>>>(input, target, slabsPerImg, (float*)d_out);
}

// round 9
// speedup vs baseline: 1.1286x; 1.0587x over previous
#include <cuda_runtime.h>

// WeightedDiceLoss (sm_103a) — swizzled hsum ring + local 3-lane hsum
// producer (no global warp scan; independent 1-step shuffles only).
// weight = 1 + 5*|boxavg31(target) - target|, zero pad, /961
// out = 1 - (2*sum(in*t*w) + 1) / (sum(in*w) + sum(t*w) + 1)

#define Wd    512
#define Hd    512
#define Rr    128
#define HALO  15
#define SLABR (Rr + 2*HALO)        // 158
#define RING  48
#define NCHUNK (Rr / 16)           // 8
#define INV_KK2 (1.0f/961.0f)

// physical column for logical column c (XOR unit-index bits)
__device__ __forceinline__ int swz(int c) { return c ^ (((c >> 5) & 7) << 2); }

__device__ float g_part[3 * 1024];
__device__ unsigned int g_count = 0;

__global__ __launch_bounds__(512, 2)
void wdice_main(const float* __restrict__ input,
                const float* __restrict__ target,
                int slabsPerImg,
                float* __restrict__ out)
{
    extern __shared__ float HS[];           // [RING][512] swizzled hsum rows
    const int tid  = threadIdx.x;
    const int wid  = tid >> 5;
    const int lane = tid & 31;
    const int img  = blockIdx.x / slabsPerImg;
    const int slab = blockIdx.x % slabsPerImg;
    const int r0   = slab * Rr;
    const size_t imgOff = (size_t)img * (size_t)(Hd * Wd);

    // ---- Producer: warp `wid` computes hsum of target row (r0-15+j) with
    // LOCAL prefixes only; window spans <=3 lanes, so one-step shuffles suffice.
    //   hsum[16L+i] = (T_{L-1} - p_{L-1}[i]) + T_L + p_{L+1}[i-1]
    auto produce = [&](int pr) {
        const int j = pr + wid;
        if (j >= SLABR) return;
        const int gr = r0 - HALO + j;
        float4* dstRow = (float4*)(HS + (j % RING) * Wd);
        const int sL = (lane >> 1) & 7;
        if (gr < 0 || gr >= Hd) {
            const float4 z = make_float4(0.f, 0.f, 0.f, 0.f);
            #pragma unroll
            for (int p = 0; p < 4; p++) dstRow[(4 * lane + p) ^ sL] = z;
            return;
        }
        float p[16];
        const float4* row = (const float4*)(target + imgOff + (size_t)gr * Wd);
        #pragma unroll
        for (int q = 0; q < 4; q++) {
            float4 f = row[lane * 4 + q];
            p[4*q+0] = f.x; p[4*q+1] = f.y; p[4*q+2] = f.z; p[4*q+3] = f.w;
        }
        #pragma unroll
        for (int i = 1; i < 16; i++) p[i] += p[i-1];     // local inclusive prefix
        const float T  = p[15];
        float Tp = __shfl_up_sync(0xffffffffu, T, 1);
        if (lane == 0) Tp = 0.f;
        const float base = Tp + T;

        float h[16];
        #pragma unroll
        for (int i = 0; i < 16; i++) {
            float pm = __shfl_up_sync(0xffffffffu, p[i], 1);   // p_{L-1}[i]
            if (lane == 0) pm = 0.f;
            h[i] = base - pm;
        }
        #pragma unroll
        for (int i = 1; i < 16; i++) {
            float pp = __shfl_down_sync(0xffffffffu, p[i-1], 1); // p_{L+1}[i-1]
            if (lane == 31) pp = 0.f;
            h[i] += pp;
        }
        #pragma unroll
        for (int q = 0; q < 4; q++)
            dstRow[(4 * lane + q) ^ sL] =
                make_float4(h[4*q], h[4*q+1], h[4*q+2], h[4*q+3]);
    };

    produce(0); produce(16); produce(32);
    __syncthreads();

    // ---- Consumer: thread = column c (fixed swizzled offset qc).
    const int c  = tid;
    const int qc = swz(c);
    float vsum = 0.f;
    #pragma unroll
    for (int j = 0; j <= 2 * HALO; j++)
        vsum += HS[j * Wd + qc];

    float aI = 0.f, aA = 0.f, aB = 0.f;
    const float* inp = input  + imgOff + (size_t)r0 * Wd + c;
    const float* tgt = target + imgOff + (size_t)r0 * Wd + c;

    #pragma unroll
    for (int ch = 0; ch < NCHUNK; ch++) {
        #pragma unroll
        for (int kk = 0; kk < 16; kk++) {
            const int k = ch * 16 + kk;
            const int jAdd = ((k + 31) % RING) * Wd;
            const int jSub = (k % RING) * Wd;

            const float t  = tgt[k * Wd];
            const float in = inp[k * Wd];
            const float w  = fmaf(5.f, fabsf(fmaf(vsum, INV_KK2, -t)), 1.f);
            const float tw = t * w;
            aI = fmaf(in, tw, aI);
            aA = fmaf(in, w,  aA);
            aB += tw;

            if (k < Rr - 1)
                vsum += (HS[jAdd + qc] - HS[jSub + qc]);
        }
        __syncthreads();
        if (ch < NCHUNK - 1) {
            produce(48 + ch * 16);
            __syncthreads();
        }
    }

    // ---- Block reduction (fixed order -> deterministic)
    #pragma unroll
    for (int o = 16; o > 0; o >>= 1) {
        aI += __shfl_down_sync(0xffffffffu, aI, o);
        aA += __shfl_down_sync(0xffffffffu, aA, o);
        aB += __shfl_down_sync(0xffffffffu, aB, o);
    }
    if (lane == 0) { HS[wid] = aI; HS[16 + wid] = aA; HS[32 + wid] = aB; }
    __syncthreads();
    __shared__ unsigned int sIsLast;
    if (tid == 0) {
        float I = 0.f, A = 0.f, B = 0.f;
        #pragma unroll
        for (int i = 0; i < 16; i++) { I += HS[i]; A += HS[16 + i]; B += HS[32 + i]; }
        g_part[blockIdx.x * 3 + 0] = I;
        g_part[blockIdx.x * 3 + 1] = A;
        g_part[blockIdx.x * 3 + 2] = B;
        __threadfence();
        sIsLast = (atomicAdd(&g_count, 1u) == gridDim.x - 1u);
    }
    __syncthreads();

    if (sIsLast) {
        const int nb = gridDim.x;
        float i = 0.f, a = 0.f, b = 0.f;
        for (int j = tid; j < nb; j += 512) {
            i += g_part[3 * j + 0];
            a += g_part[3 * j + 1];
            b += g_part[3 * j + 2];
        }
        #pragma unroll
        for (int o = 16; o > 0; o >>= 1) {
            i += __shfl_down_sync(0xffffffffu, i, o);
            a += __shfl_down_sync(0xffffffffu, a, o);
            b += __shfl_down_sync(0xffffffffu, b, o);
        }
        __syncthreads();
        if (lane == 0) { HS[wid] = i; HS[16 + wid] = a; HS[32 + wid] = b; }
        __syncthreads();
        if (tid == 0) {
            float I = 0.f, A = 0.f, B = 0.f;
            #pragma unroll
            for (int q = 0; q < 16; q++) { I += HS[q]; A += HS[16 + q]; B += HS[32 + q]; }
            out[0] = 1.f - (2.f * I + 1.f) / (A + B + 1.f);
            g_count = 0;
        }
    }
}

extern "C" void kernel_launch(void* const* d_in, const int* in_sizes, int n_in,
                              void* d_out, int out_size)
{
    const float* input  = (const float*)d_in[0];
    const float* target = (const float*)d_in[1];
    const int nImg = in_sizes[0] / (Hd * Wd);
    const int slabsPerImg = Hd / Rr;               // 4
    const int grid = nImg * slabsPerImg;           // 256
    const size_t smem = (size_t)RING * Wd * sizeof(float);   // 98304 B

    cudaFuncSetAttribute(wdice_main,
                         cudaFuncAttributeMaxDynamicSharedMemorySize, (int)smem);
    wdice_main<<<grid, 512, smem>>>(input, target, slabsPerImg, (float*)d_out);
}